// round 1
// baseline (speedup 1.0000x reference)
#include <cuda_runtime.h>

#define BB 2
#define NN 2048
#define DD 1024
#define HH 16
#define HDIM 64
#define DH2 32
#define MM (BB*NN)      /* 4096 rows of x */
#define N3 (3*DD)       /* 3072 qkv cols  */

// Scratch (no allocations allowed): q,k,v in [b,h,n,hd] layout, o in [b,n,d]
__device__ __align__(16) float g_q[BB*HH*NN*HDIM];
__device__ __align__(16) float g_k[BB*HH*NN*HDIM];
__device__ __align__(16) float g_v[BB*HH*NN*HDIM];
__device__ __align__(16) float g_o[MM*DD];

// ---------------------------------------------------------------------------
// Kernel 1: qkv = x @ W_qkv  (M=4096, N=3072, K=1024), split heads + RoPE.
// 128x128 block tile, 8x8 per thread, BK=8.
// ---------------------------------------------------------------------------
__global__ __launch_bounds__(256) void k_qkv(const float* __restrict__ x,
                                             const float* __restrict__ W,
                                             const float* __restrict__ fc) {
    __shared__ float As[8][132];
    __shared__ float Bs[8][128];
    const int t   = threadIdx.x;
    const int tx  = t & 15, ty = t >> 4;
    const int row0 = blockIdx.y * 128, col0 = blockIdx.x * 128;
    const int arow = t >> 1, ak = (t & 1) * 4;   // A: 128x8 tile, 1 float4/thread
    const int brow = t >> 5, bc = (t & 31) * 4;  // B: 8x128 tile, 1 float4/thread
    float acc[8][8] = {};

    for (int k0 = 0; k0 < 1024; k0 += 8) {
        float4 av = *(const float4*)(x + (row0 + arow) * 1024 + k0 + ak);
        float4 bv = *(const float4*)(W + (k0 + brow) * 3072 + col0 + bc);
        __syncthreads();
        As[ak + 0][arow] = av.x; As[ak + 1][arow] = av.y;
        As[ak + 2][arow] = av.z; As[ak + 3][arow] = av.w;
        *(float4*)(&Bs[brow][bc]) = bv;
        __syncthreads();
#pragma unroll
        for (int kk = 0; kk < 8; kk++) {
            float a[8], b[8];
#pragma unroll
            for (int i = 0; i < 8; i++) a[i] = As[kk][ty * 8 + i];
#pragma unroll
            for (int j = 0; j < 8; j++) b[j] = Bs[kk][tx * 8 + j];
#pragma unroll
            for (int i = 0; i < 8; i++)
#pragma unroll
                for (int j = 0; j < 8; j++) acc[i][j] += a[i] * b[j];
        }
    }

    // Epilogue: scatter into g_q/g_k/g_v with RoPE on q,k.
    const int cbase = col0 + tx * 8;
    const int which = cbase / 1024;                 // 0=q 1=k 2=v (no crossing)
    float* dst = (which == 0) ? g_q : (which == 1) ? g_k : g_v;
#pragma unroll
    for (int i = 0; i < 8; i++) {
        const int m = row0 + ty * 8 + i;
        const int b_ = m >> 11, n = m & 2047;
#pragma unroll
        for (int j = 0; j < 8; j += 2) {
            const int c  = cbase + j;
            const int d  = c & 1023;
            const int h  = d >> 6, hd = d & 63;
            const int off = (((b_ * HH + h) * NN + n) * HDIM + hd);
            const float v0 = acc[i][j], v1 = acc[i][j + 1];
            if (which < 2) {
                const int jj = hd >> 1;
                const float cs = fc[n * 64 + jj * 2];
                const float sn = fc[n * 64 + jj * 2 + 1];
                dst[off]     = v0 * cs - v1 * sn;
                dst[off + 1] = v0 * sn + v1 * cs;
            } else {
                dst[off]     = v0;
                dst[off + 1] = v1;
            }
        }
    }
}

// ---------------------------------------------------------------------------
// Kernel 2a: S = scale * q @ k^T per (b,h).  M=N=2048, K=64.
// ---------------------------------------------------------------------------
__global__ __launch_bounds__(256) void k_scores(float* __restrict__ attn) {
    __shared__ float Qs[16][132];
    __shared__ float Ks[16][132];
    const int t  = threadIdx.x;
    const int tx = t & 15, ty = t >> 4;
    const int bh = blockIdx.z;
    const int i0 = blockIdx.y * 128, j0 = blockIdx.x * 128;
    const float* q  = g_q + (size_t)bh * NN * HDIM;
    const float* kp = g_k + (size_t)bh * NN * HDIM;
    const int lrow = t >> 1, lk = (t & 1) * 8;
    float acc[8][8] = {};

    for (int k0 = 0; k0 < HDIM; k0 += 16) {
        float4 q0 = *(const float4*)(q  + (i0 + lrow) * HDIM + k0 + lk);
        float4 q1 = *(const float4*)(q  + (i0 + lrow) * HDIM + k0 + lk + 4);
        float4 c0 = *(const float4*)(kp + (j0 + lrow) * HDIM + k0 + lk);
        float4 c1 = *(const float4*)(kp + (j0 + lrow) * HDIM + k0 + lk + 4);
        __syncthreads();
        Qs[lk + 0][lrow] = q0.x; Qs[lk + 1][lrow] = q0.y;
        Qs[lk + 2][lrow] = q0.z; Qs[lk + 3][lrow] = q0.w;
        Qs[lk + 4][lrow] = q1.x; Qs[lk + 5][lrow] = q1.y;
        Qs[lk + 6][lrow] = q1.z; Qs[lk + 7][lrow] = q1.w;
        Ks[lk + 0][lrow] = c0.x; Ks[lk + 1][lrow] = c0.y;
        Ks[lk + 2][lrow] = c0.z; Ks[lk + 3][lrow] = c0.w;
        Ks[lk + 4][lrow] = c1.x; Ks[lk + 5][lrow] = c1.y;
        Ks[lk + 6][lrow] = c1.z; Ks[lk + 7][lrow] = c1.w;
        __syncthreads();
#pragma unroll
        for (int kk = 0; kk < 16; kk++) {
            float a[8], b[8];
#pragma unroll
            for (int i = 0; i < 8; i++) a[i] = Qs[kk][ty * 8 + i];
#pragma unroll
            for (int j = 0; j < 8; j++) b[j] = Ks[kk][tx * 8 + j];
#pragma unroll
            for (int i = 0; i < 8; i++)
#pragma unroll
                for (int j = 0; j < 8; j++) acc[i][j] += a[i] * b[j];
        }
    }

    const float s = 0.03125f;  // D^-0.5
#pragma unroll
    for (int i = 0; i < 8; i++) {
        const int gi = i0 + ty * 8 + i;
        float* dst = attn + ((size_t)bh * NN + gi) * NN + j0 + tx * 8;
        float4 v0 = make_float4(acc[i][0] * s, acc[i][1] * s, acc[i][2] * s, acc[i][3] * s);
        float4 v1 = make_float4(acc[i][4] * s, acc[i][5] * s, acc[i][6] * s, acc[i][7] * s);
        *(float4*)dst       = v0;
        *(float4*)(dst + 4) = v1;
    }
}

// ---------------------------------------------------------------------------
// Kernel 2b: row softmax in place on attn region. 1 block = 1 row of 2048.
// ---------------------------------------------------------------------------
__global__ __launch_bounds__(256) void k_softmax(float* __restrict__ attn) {
    float* p = attn + (size_t)blockIdx.x * NN;
    const int t = threadIdx.x;
    float4 a = *(float4*)(p + t * 4);
    float4 b = *(float4*)(p + 1024 + t * 4);
    float m = fmaxf(fmaxf(fmaxf(a.x, a.y), fmaxf(a.z, a.w)),
                    fmaxf(fmaxf(b.x, b.y), fmaxf(b.z, b.w)));
    __shared__ float red[256];
    red[t] = m;
    __syncthreads();
    for (int o = 128; o; o >>= 1) {
        if (t < o) red[t] = fmaxf(red[t], red[t + o]);
        __syncthreads();
    }
    m = red[0];
    __syncthreads();
    a.x = __expf(a.x - m); a.y = __expf(a.y - m);
    a.z = __expf(a.z - m); a.w = __expf(a.w - m);
    b.x = __expf(b.x - m); b.y = __expf(b.y - m);
    b.z = __expf(b.z - m); b.w = __expf(b.w - m);
    float s = a.x + a.y + a.z + a.w + b.x + b.y + b.z + b.w;
    red[t] = s;
    __syncthreads();
    for (int o = 128; o; o >>= 1) {
        if (t < o) red[t] += red[t + o];
        __syncthreads();
    }
    const float inv = 1.0f / red[0];
    a.x *= inv; a.y *= inv; a.z *= inv; a.w *= inv;
    b.x *= inv; b.y *= inv; b.z *= inv; b.w *= inv;
    *(float4*)(p + t * 4)        = a;
    *(float4*)(p + 1024 + t * 4) = b;
}

// ---------------------------------------------------------------------------
// Kernel 2c: out_head = attn @ v per (b,h). M=2048, N=64, K=2048.
// 128x64 block tile, 8x4 per thread, BK=16. Writes g_o in [b,n,d] layout.
// ---------------------------------------------------------------------------
__global__ __launch_bounds__(256) void k_av(const float* __restrict__ attn) {
    __shared__ float As[16][132];
    __shared__ float Vs[16][64];
    const int t  = threadIdx.x;
    const int tx = t & 15, ty = t >> 4;
    const int bh = blockIdx.z;
    const int i0 = blockIdx.y * 128;
    const float* a = attn + (size_t)bh * NN * NN;
    const float* v = g_v + (size_t)bh * NN * HDIM;
    const int lrow = t >> 1, lk = (t & 1) * 8;
    const int vr = t >> 4, vc = (t & 15) * 4;
    float acc[8][4] = {};

    for (int k0 = 0; k0 < NN; k0 += 16) {
        float4 a0 = *(const float4*)(a + (size_t)(i0 + lrow) * NN + k0 + lk);
        float4 a1 = *(const float4*)(a + (size_t)(i0 + lrow) * NN + k0 + lk + 4);
        float4 vv = *(const float4*)(v + (k0 + vr) * HDIM + vc);
        __syncthreads();
        As[lk + 0][lrow] = a0.x; As[lk + 1][lrow] = a0.y;
        As[lk + 2][lrow] = a0.z; As[lk + 3][lrow] = a0.w;
        As[lk + 4][lrow] = a1.x; As[lk + 5][lrow] = a1.y;
        As[lk + 6][lrow] = a1.z; As[lk + 7][lrow] = a1.w;
        *(float4*)(&Vs[vr][vc]) = vv;
        __syncthreads();
#pragma unroll
        for (int kk = 0; kk < 16; kk++) {
            float ar[8], br[4];
#pragma unroll
            for (int i = 0; i < 8; i++) ar[i] = As[kk][ty * 8 + i];
#pragma unroll
            for (int j = 0; j < 4; j++) br[j] = Vs[kk][tx * 4 + j];
#pragma unroll
            for (int i = 0; i < 8; i++)
#pragma unroll
                for (int j = 0; j < 4; j++) acc[i][j] += ar[i] * br[j];
        }
    }

    const int b_ = bh >> 4, h = bh & 15;
#pragma unroll
    for (int i = 0; i < 8; i++) {
        const int gi = i0 + ty * 8 + i;
        float* dst = g_o + ((size_t)(b_ * NN + gi)) * DD + h * HDIM + tx * 4;
        *(float4*)dst = make_float4(acc[i][0], acc[i][1], acc[i][2], acc[i][3]);
    }
}

// ---------------------------------------------------------------------------
// Kernel 3: out = g_o @ W_out + b_out. M=4096, N=1024, K=1024.
// ---------------------------------------------------------------------------
__global__ __launch_bounds__(256) void k_proj(const float* __restrict__ W,
                                              const float* __restrict__ bias,
                                              float* __restrict__ out) {
    __shared__ float As[8][132];
    __shared__ float Bs[8][128];
    const int t   = threadIdx.x;
    const int tx  = t & 15, ty = t >> 4;
    const int row0 = blockIdx.y * 128, col0 = blockIdx.x * 128;
    const int arow = t >> 1, ak = (t & 1) * 4;
    const int brow = t >> 5, bc = (t & 31) * 4;
    float acc[8][8] = {};

    for (int k0 = 0; k0 < 1024; k0 += 8) {
        float4 av = *(const float4*)(g_o + (row0 + arow) * 1024 + k0 + ak);
        float4 bv = *(const float4*)(W + (k0 + brow) * 1024 + col0 + bc);
        __syncthreads();
        As[ak + 0][arow] = av.x; As[ak + 1][arow] = av.y;
        As[ak + 2][arow] = av.z; As[ak + 3][arow] = av.w;
        *(float4*)(&Bs[brow][bc]) = bv;
        __syncthreads();
#pragma unroll
        for (int kk = 0; kk < 8; kk++) {
            float a[8], b[8];
#pragma unroll
            for (int i = 0; i < 8; i++) a[i] = As[kk][ty * 8 + i];
#pragma unroll
            for (int j = 0; j < 8; j++) b[j] = Bs[kk][tx * 8 + j];
#pragma unroll
            for (int i = 0; i < 8; i++)
#pragma unroll
                for (int j = 0; j < 8; j++) acc[i][j] += a[i] * b[j];
        }
    }

    const int cbase = col0 + tx * 8;
    float bb[8];
#pragma unroll
    for (int j = 0; j < 8; j++) bb[j] = bias[cbase + j];
#pragma unroll
    for (int i = 0; i < 8; i++) {
        const int m = row0 + ty * 8 + i;
        float* dst = out + (size_t)m * 1024 + cbase;
        float4 v0 = make_float4(acc[i][0] + bb[0], acc[i][1] + bb[1],
                                acc[i][2] + bb[2], acc[i][3] + bb[3]);
        float4 v1 = make_float4(acc[i][4] + bb[4], acc[i][5] + bb[5],
                                acc[i][6] + bb[6], acc[i][7] + bb[7]);
        *(float4*)dst       = v0;
        *(float4*)(dst + 4) = v1;
    }
}

// ---------------------------------------------------------------------------
extern "C" void kernel_launch(void* const* d_in, const int* in_sizes, int n_in,
                              void* d_out, int out_size) {
    const float* x    = (const float*)d_in[0];
    const float* fc   = (const float*)d_in[1];
    const float* Wqkv = (const float*)d_in[2];
    const float* Wout = (const float*)d_in[3];
    const float* bout = (const float*)d_in[4];
    float* out  = (float*)d_out;
    float* attn = out + (size_t)MM * DD;   // tuple layout: out first, then attn

    k_qkv   <<<dim3(N3 / 128, MM / 128), 256>>>(x, Wqkv, fc);
    k_scores<<<dim3(NN / 128, NN / 128, BB * HH), 256>>>(attn);
    k_softmax<<<BB * HH * NN, 256>>>(attn);
    k_av    <<<dim3(1, NN / 128, BB * HH), 256>>>(attn);
    k_proj  <<<dim3(1024 / 128, MM / 128), 256>>>(Wout, bout, out);
}